// round 1
// baseline (speedup 1.0000x reference)
#include <cuda_runtime.h>
#include <math.h>

#define D_DIM 256
#define NP 64
#define M_DIM 1024
#define NH 8
#define RR 32
#define KENC 192
#define GAMMA 0.25f

// ---------------------------------------------------------------------------
// block reduction over 256 threads (fixed order -> deterministic)
// ---------------------------------------------------------------------------
__device__ __forceinline__ float block_reduce_256(float v, float* red) {
#pragma unroll
    for (int o = 16; o > 0; o >>= 1) v += __shfl_xor_sync(0xffffffffu, v, o);
    int w = threadIdx.x >> 5;
    if ((threadIdx.x & 31) == 0) red[w] = v;
    __syncthreads();
    if (threadIdx.x < 8) {
        v = red[threadIdx.x];
#pragma unroll
        for (int o = 4; o > 0; o >>= 1) v += __shfl_xor_sync(0x000000ffu, v, o);
    }
    return v;  // valid on thread 0
}

// ---------------------------------------------------------------------------
// Kernel X: quad_x - phi_vis - phi_enc      (one CTA per batch element)
//   t[p,k] = sum_d z[p,d] * Wenc[d,k]   (64 x 192 GEMM, K=256)
//   contribution = sum_pixels x*(0.5*x - vb - t[p(pix),k(pix)])
// ---------------------------------------------------------------------------
extern "C" __global__ void __launch_bounds__(256)
kx_kernel(const float* __restrict__ x, const float* __restrict__ z,
          const float* __restrict__ Wenc, const float* __restrict__ vb,
          float* __restrict__ out) {
    extern __shared__ float sm[];
    float* zs  = sm;                 // 64 x 260 (padded)   = 16640 floats
    float* ts  = zs + 64 * 260;      // 64 x 196 (padded)   = 12544 floats
    float* ws  = ts + 64 * 196;      // 32 x 64             = 2048 floats
    float* red = ws + 32 * 64;       // 32

    int b = blockIdx.x, tid = threadIdx.x;
    const float4* z4 = (const float4*)(z + (size_t)b * (NP * D_DIM));
#pragma unroll
    for (int i = 0; i < 16; i++) {
        int f4 = tid + i * 256;
        int base = f4 * 4, p = base >> 8, d = base & 255;
        *(float4*)&zs[p * 260 + d] = z4[f4];
    }
    __syncthreads();

    int tm = tid & 15, tp = tid >> 4;     // 16 m-threads (4 cols each), 16 p-threads (4 rows each)
    for (int mt = 0; mt < KENC; mt += 64) {
        float acc[4][4];
#pragma unroll
        for (int pi = 0; pi < 4; pi++)
#pragma unroll
            for (int j = 0; j < 4; j++) acc[pi][j] = 0.f;

        for (int k0 = 0; k0 < D_DIM; k0 += 32) {
#pragma unroll
            for (int i = 0; i < 2; i++) {
                int f4 = tid + i * 256;
                int row = f4 >> 4, c4 = f4 & 15;
                ((float4*)ws)[f4] = *(const float4*)(Wenc + (k0 + row) * KENC + mt + c4 * 4);
            }
            __syncthreads();
            for (int kq = 0; kq < 8; kq++) {
                float4 w0 = ((float4*)ws)[(kq * 4 + 0) * 16 + tm];
                float4 w1 = ((float4*)ws)[(kq * 4 + 1) * 16 + tm];
                float4 w2 = ((float4*)ws)[(kq * 4 + 2) * 16 + tm];
                float4 w3 = ((float4*)ws)[(kq * 4 + 3) * 16 + tm];
#pragma unroll
                for (int pi = 0; pi < 4; pi++) {
                    float4 zv = *(const float4*)&zs[(tp * 4 + pi) * 260 + k0 + kq * 4];
                    acc[pi][0] += zv.x * w0.x + zv.y * w1.x + zv.z * w2.x + zv.w * w3.x;
                    acc[pi][1] += zv.x * w0.y + zv.y * w1.y + zv.z * w2.y + zv.w * w3.y;
                    acc[pi][2] += zv.x * w0.z + zv.y * w1.z + zv.z * w2.z + zv.w * w3.z;
                    acc[pi][3] += zv.x * w0.w + zv.y * w1.w + zv.z * w2.w + zv.w * w3.w;
                }
            }
            __syncthreads();
        }
#pragma unroll
        for (int pi = 0; pi < 4; pi++)
#pragma unroll
            for (int j = 0; j < 4; j++)
                ts[(tp * 4 + pi) * 196 + mt + tm * 4 + j] = acc[pi][j];
    }
    __syncthreads();

    const float* xb = x + (size_t)b * 12288;
    float local = 0.f;
    for (int idx = tid; idx < 12288; idx += 256) {
        float xv = xb[idx], vbv = vb[idx];
        int c = idx >> 12, rem = idx & 4095, ii = rem >> 6, jj = rem & 63;
        int p = ((ii >> 3) << 3) + (jj >> 3);
        int k = (c << 6) + ((ii & 7) << 3) + (jj & 7);
        local += xv * (0.5f * xv - vbv - ts[p * 196 + k]);
    }
    __syncthreads();
    float tot = block_reduce_256(local, red);
    if (tid == 0) out[b] = tot;   // first writer (out is poisoned)
}

// ---------------------------------------------------------------------------
// Kernel Z: quad_z - phi_bias - phi_pos - phi_mem   (one CTA per batch)
//   phi_mem = sum relu(z @ Wm)^2 ; 64x1024 output in 8 tiles of 128 cols
// ---------------------------------------------------------------------------
extern "C" __global__ void __launch_bounds__(256, 2)
kz_kernel(const float* __restrict__ z, const float* __restrict__ eb,
          const float* __restrict__ pos, const float* __restrict__ Wm,
          float* __restrict__ out) {
    extern __shared__ float sm[];
    float* zs  = sm;             // 64 x 256 = 16384 floats (broadcast access -> no pad)
    float* ws  = zs + 16384;     // 32 x 128 = 4096
    float* red = ws + 4096;      // 32

    int b = blockIdx.x, tid = threadIdx.x;
    const float4* z4 = (const float4*)(z + (size_t)b * (NP * D_DIM));
    const float4* p4 = (const float4*)pos;
    float qz = 0.f, pb = 0.f, pp = 0.f;
#pragma unroll
    for (int i = 0; i < 16; i++) {
        int f4 = tid + i * 256;
        float4 zv = z4[f4];
        ((float4*)zs)[f4] = zv;
        int d = (f4 * 4) & 255;
        float4 ev = *(const float4*)(eb + d);
        float4 pv = p4[f4];
        qz += 0.5f * (zv.x * zv.x + zv.y * zv.y + zv.z * zv.z + zv.w * zv.w);
        pb += zv.x * ev.x + zv.y * ev.y + zv.z * ev.z + zv.w * ev.w;
        pp += zv.x * pv.x + zv.y * pv.y + zv.z * pv.z + zv.w * pv.w;
    }
    __syncthreads();

    int tm = tid & 31, tp = tid >> 5;   // 32 m-threads (4 cols), 8 p-threads (8 rows)
    float pm = 0.f;
    for (int mt = 0; mt < M_DIM; mt += 128) {
        float acc[8][4];
#pragma unroll
        for (int pi = 0; pi < 8; pi++)
#pragma unroll
            for (int j = 0; j < 4; j++) acc[pi][j] = 0.f;

        for (int k0 = 0; k0 < D_DIM; k0 += 32) {
#pragma unroll
            for (int i = 0; i < 4; i++) {
                int f4 = tid + i * 256;
                int row = f4 >> 5, c4 = f4 & 31;
                ((float4*)ws)[f4] = *(const float4*)(Wm + (k0 + row) * M_DIM + mt + c4 * 4);
            }
            __syncthreads();
            for (int kq = 0; kq < 8; kq++) {
                float4 w0 = ((float4*)ws)[(kq * 4 + 0) * 32 + tm];
                float4 w1 = ((float4*)ws)[(kq * 4 + 1) * 32 + tm];
                float4 w2 = ((float4*)ws)[(kq * 4 + 2) * 32 + tm];
                float4 w3 = ((float4*)ws)[(kq * 4 + 3) * 32 + tm];
#pragma unroll
                for (int pi = 0; pi < 8; pi++) {
                    float4 zv = *(const float4*)&zs[(tp * 8 + pi) * 256 + k0 + kq * 4];
                    acc[pi][0] += zv.x * w0.x + zv.y * w1.x + zv.z * w2.x + zv.w * w3.x;
                    acc[pi][1] += zv.x * w0.y + zv.y * w1.y + zv.z * w2.y + zv.w * w3.y;
                    acc[pi][2] += zv.x * w0.z + zv.y * w1.z + zv.z * w2.z + zv.w * w3.z;
                    acc[pi][3] += zv.x * w0.w + zv.y * w1.w + zv.z * w2.w + zv.w * w3.w;
                }
            }
            __syncthreads();
        }
#pragma unroll
        for (int pi = 0; pi < 8; pi++)
#pragma unroll
            for (int j = 0; j < 4; j++) {
                float v = fmaxf(acc[pi][j], 0.f);
                pm += v * v;
            }
    }
    float tot = block_reduce_256(qz - pb - pp - pm, red);
    if (tid == 0) out[b] += tot;
}

// ---------------------------------------------------------------------------
// Kernel ATT: -phi_att    (one CTA per batch; loop over 8 heads)
//   q = z @ WQ_h^T, k = z @ WK_h^T (64x32 each), A = q k^T (64x64),
//   phi_att += sum_m LSE_n(GAMMA*A[m,n]) / GAMMA
// ---------------------------------------------------------------------------
extern "C" __global__ void __launch_bounds__(256)
ka_kernel(const float* __restrict__ z, const float* __restrict__ WQ,
          const float* __restrict__ WK, float* __restrict__ out) {
    extern __shared__ float sm[];
    float* zs  = sm;               // 64 x 260 = 16640
    float* wq  = zs + 16640;       // 256 x 36 = 9216 (transposed, d-major)
    float* wk  = wq + 9216;        // 9216
    float* qs  = wk + 9216;        // 64 x 36 = 2304
    float* ks  = qs + 2304;        // 2304
    float* red = ks + 2304;        // 32

    int b = blockIdx.x, tid = threadIdx.x;
    const float4* z4 = (const float4*)(z + (size_t)b * (NP * D_DIM));
#pragma unroll
    for (int i = 0; i < 16; i++) {
        int f4 = tid + i * 256;
        int base = f4 * 4, p = base >> 8, d = base & 255;
        *(float4*)&zs[p * 260 + d] = z4[f4];
    }
    __syncthreads();

    float att = 0.f;
    int tm = tid & 7, tp = tid >> 3;   // gemm mapping: 8 r-threads (4 each), 32 p-threads (2 each)
    int m = tid >> 2, nq = tid & 3;    // logits mapping

    for (int h = 0; h < NH; h++) {
        // stage WQ_h, WK_h transposed: wq[d*36 + r]
        for (int f = tid; f < RR * D_DIM; f += 256) {
            int r = f >> 8, d = f & 255;
            wq[d * 36 + r] = WQ[(h * RR + r) * D_DIM + d];
            wk[d * 36 + r] = WK[(h * RR + r) * D_DIM + d];
        }
        __syncthreads();

        float aq[2][4], ak[2][4];
#pragma unroll
        for (int pi = 0; pi < 2; pi++)
#pragma unroll
            for (int j = 0; j < 4; j++) { aq[pi][j] = 0.f; ak[pi][j] = 0.f; }

#pragma unroll 4
        for (int dq = 0; dq < 64; dq++) {
            int d = dq * 4;
            float4 q0 = *(const float4*)&wq[(d + 0) * 36 + tm * 4];
            float4 q1 = *(const float4*)&wq[(d + 1) * 36 + tm * 4];
            float4 q2 = *(const float4*)&wq[(d + 2) * 36 + tm * 4];
            float4 q3 = *(const float4*)&wq[(d + 3) * 36 + tm * 4];
            float4 k0 = *(const float4*)&wk[(d + 0) * 36 + tm * 4];
            float4 k1 = *(const float4*)&wk[(d + 1) * 36 + tm * 4];
            float4 k2 = *(const float4*)&wk[(d + 2) * 36 + tm * 4];
            float4 k3 = *(const float4*)&wk[(d + 3) * 36 + tm * 4];
#pragma unroll
            for (int pi = 0; pi < 2; pi++) {
                float4 zv = *(const float4*)&zs[(tp * 2 + pi) * 260 + d];
                aq[pi][0] += zv.x * q0.x + zv.y * q1.x + zv.z * q2.x + zv.w * q3.x;
                aq[pi][1] += zv.x * q0.y + zv.y * q1.y + zv.z * q2.y + zv.w * q3.y;
                aq[pi][2] += zv.x * q0.z + zv.y * q1.z + zv.z * q2.z + zv.w * q3.z;
                aq[pi][3] += zv.x * q0.w + zv.y * q1.w + zv.z * q2.w + zv.w * q3.w;
                ak[pi][0] += zv.x * k0.x + zv.y * k1.x + zv.z * k2.x + zv.w * k3.x;
                ak[pi][1] += zv.x * k0.y + zv.y * k1.y + zv.z * k2.y + zv.w * k3.y;
                ak[pi][2] += zv.x * k0.z + zv.y * k1.z + zv.z * k2.z + zv.w * k3.z;
                ak[pi][3] += zv.x * k0.w + zv.y * k1.w + zv.z * k2.w + zv.w * k3.w;
            }
        }
#pragma unroll
        for (int pi = 0; pi < 2; pi++)
#pragma unroll
            for (int j = 0; j < 4; j++) {
                qs[(tp * 2 + pi) * 36 + tm * 4 + j] = aq[pi][j];
                ks[(tp * 2 + pi) * 36 + tm * 4 + j] = ak[pi][j];
            }
        __syncthreads();

        // logits + LSE: thread -> (m = tid/4, n in {nq + 4*nn})
        float qreg[32];
#pragma unroll
        for (int r4 = 0; r4 < 8; r4++) {
            float4 v = *(const float4*)&qs[m * 36 + r4 * 4];
            qreg[r4 * 4 + 0] = v.x; qreg[r4 * 4 + 1] = v.y;
            qreg[r4 * 4 + 2] = v.z; qreg[r4 * 4 + 3] = v.w;
        }
        float a[16];
#pragma unroll
        for (int nn = 0; nn < 16; nn++) {
            int n = nq + nn * 4;
            float s = 0.f;
#pragma unroll
            for (int r4 = 0; r4 < 8; r4++) {
                float4 kv = *(const float4*)&ks[n * 36 + r4 * 4];
                s += qreg[r4 * 4 + 0] * kv.x + qreg[r4 * 4 + 1] * kv.y +
                     qreg[r4 * 4 + 2] * kv.z + qreg[r4 * 4 + 3] * kv.w;
            }
            a[nn] = s;
        }
        float amax = a[0];
#pragma unroll
        for (int nn = 1; nn < 16; nn++) amax = fmaxf(amax, a[nn]);
        amax = fmaxf(amax, __shfl_xor_sync(0xffffffffu, amax, 1));
        amax = fmaxf(amax, __shfl_xor_sync(0xffffffffu, amax, 2));
        float se = 0.f;
#pragma unroll
        for (int nn = 0; nn < 16; nn++) se += __expf(GAMMA * (a[nn] - amax));
        se += __shfl_xor_sync(0xffffffffu, se, 1);
        se += __shfl_xor_sync(0xffffffffu, se, 2);
        if (nq == 0) att += amax + __logf(se) * (1.f / GAMMA);
        __syncthreads();
    }
    float tot = block_reduce_256(att, red);
    if (tid == 0) out[b] -= tot;
}

// ---------------------------------------------------------------------------
extern "C" void kernel_launch(void* const* d_in, const int* in_sizes, int n_in,
                              void* d_out, int out_size) {
    (void)in_sizes; (void)n_in; (void)out_size;
    const float* x   = (const float*)d_in[0];
    const float* z   = (const float*)d_in[1];
    const float* We  = (const float*)d_in[2];
    const float* ebv = (const float*)d_in[3];
    const float* vb  = (const float*)d_in[4];
    const float* pos = (const float*)d_in[5];
    const float* Wm  = (const float*)d_in[6];
    const float* WQ  = (const float*)d_in[7];
    const float* WK  = (const float*)d_in[8];
    float* out = (float*)d_out;

    size_t shx = (size_t)(16640 + 12544 + 2048 + 32) * sizeof(float);   // ~125 KB
    size_t shz = (size_t)(16384 + 4096 + 32) * sizeof(float);           // ~82 KB
    size_t sha = (size_t)(16640 + 9216 * 2 + 2304 * 2 + 32) * sizeof(float); // ~159 KB

    cudaFuncSetAttribute(kx_kernel, cudaFuncAttributeMaxDynamicSharedMemorySize, (int)shx);
    cudaFuncSetAttribute(kz_kernel, cudaFuncAttributeMaxDynamicSharedMemorySize, (int)shz);
    cudaFuncSetAttribute(ka_kernel, cudaFuncAttributeMaxDynamicSharedMemorySize, (int)sha);

    kx_kernel<<<1024, 256, shx>>>(x, z, We, vb, out);
    kz_kernel<<<1024, 256, shz>>>(z, ebv, pos, Wm, out);
    ka_kernel<<<1024, 256, sha>>>(z, WQ, WK, out);
}

// round 3
// speedup vs baseline: 6.5922x; 6.5922x over previous
#include <cuda_runtime.h>
#include <cuda_bf16.h>
#include <stdint.h>
#include <math.h>

#define GAMMA 0.25f

// ---------------------------------------------------------------------------
// device scratch (static — no cudaMalloc allowed)
// ---------------------------------------------------------------------------
__device__ __align__(16) __nv_bfloat16 g_zbf[65536 * 256];       // z in bf16
__device__ __align__(16) __nv_bfloat16 g_Bg[14 * 128 * 256];     // 14 B tiles [n][k]
__device__ __align__(16) float g_q[65536 * 256];                 // Q scratch
__device__ __align__(16) float g_k[65536 * 256];                 // K scratch
__device__ __align__(16) float g_enc[65536 * 256];               // enc scratch (cols<192 valid)
__device__ float g_memsum[1024 * 8];                             // per-batch relu^2 partials

__device__ __forceinline__ uint32_t smem_u32(const void* p) {
    uint32_t a;
    asm("{ .reg .u64 t; cvta.to.shared.u64 t, %1; cvt.u32.u64 %0, t; }" : "=r"(a) : "l"(p));
    return a;
}

#define LDMX4(r0, r1, r2, r3, addr) \
    asm volatile("ldmatrix.sync.aligned.m8n8.x4.shared.b16 {%0,%1,%2,%3}, [%4];" \
                 : "=r"(r0), "=r"(r1), "=r"(r2), "=r"(r3) : "r"(addr))

#define MMA16816(d, a, b) \
    asm volatile("mma.sync.aligned.m16n8k16.row.col.f32.bf16.bf16.f32 " \
                 "{%0,%1,%2,%3}, {%4,%5,%6,%7}, {%8,%9}, {%0,%1,%2,%3};" \
                 : "+f"((d)[0]), "+f"((d)[1]), "+f"((d)[2]), "+f"((d)[3]) \
                 : "r"((a)[0]), "r"((a)[1]), "r"((a)[2]), "r"((a)[3]), \
                   "r"((b)[0]), "r"((b)[1]))

// ---------------------------------------------------------------------------
__device__ __forceinline__ float block_reduce_256(float v, float* red) {
#pragma unroll
    for (int o = 16; o > 0; o >>= 1) v += __shfl_xor_sync(0xffffffffu, v, o);
    int w = threadIdx.x >> 5;
    if ((threadIdx.x & 31) == 0) red[w] = v;
    __syncthreads();
    if (threadIdx.x < 8) {
        v = red[threadIdx.x];
#pragma unroll
        for (int o = 4; o > 0; o >>= 1) v += __shfl_xor_sync(0x000000ffu, v, o);
    }
    return v;
}

// ---------------------------------------------------------------------------
// kprepA: z f32 -> bf16 dense [row][k]
// ---------------------------------------------------------------------------
extern "C" __global__ void __launch_bounds__(256)
kprepA(const float* __restrict__ z) {
    size_t f = ((size_t)blockIdx.x * 256 + threadIdx.x) * 8;   // grid 8192
    float4 v0 = *(const float4*)(z + f);
    float4 v1 = *(const float4*)(z + f + 4);
    uint4 pk;
    __nv_bfloat162 t;
    t = __floats2bfloat162_rn(v0.x, v0.y); pk.x = *(uint32_t*)&t;
    t = __floats2bfloat162_rn(v0.z, v0.w); pk.y = *(uint32_t*)&t;
    t = __floats2bfloat162_rn(v1.x, v1.y); pk.z = *(uint32_t*)&t;
    t = __floats2bfloat162_rn(v1.z, v1.w); pk.w = *(uint32_t*)&t;
    *(uint4*)(g_zbf + f) = pk;
}

// ---------------------------------------------------------------------------
// kprepB: build 14 dense bf16 B tiles [n][k], k=0..255 contiguous.
//   nt<8 : Wm[k][nt*128+n]
//   nt 8,9 : WQ[(nt-8)*128+n][k]      nt 10,11 : WK[(nt-10)*128+n][k]
//   nt 12,13 : ng=(nt-12)*128+n; ng<192 ? Wenc[k][ng] : 0
// ---------------------------------------------------------------------------
extern "C" __global__ void __launch_bounds__(256)
kprepB(const float* __restrict__ Wm, const float* __restrict__ WQ,
       const float* __restrict__ WK, const float* __restrict__ We) {
    int nt = blockIdx.x;
    __nv_bfloat16* img = g_Bg + (size_t)nt * 128 * 256;
#pragma unroll
    for (int i = 0; i < 8; i++) {
        int f = (blockIdx.y * 256 + threadIdx.x) * 8 + i;   // grid.y = 16
        int n = f >> 8, k = f & 255;
        float v;
        if (nt < 8)        v = Wm[k * 1024 + nt * 128 + n];
        else if (nt < 10)  v = WQ[((nt - 8) * 128 + n) * 256 + k];
        else if (nt < 12)  v = WK[((nt - 10) * 128 + n) * 256 + k];
        else {
            int ng = (nt - 12) * 128 + n;
            v = (ng < 192) ? We[k * 192 + ng] : 0.f;
        }
        img[f] = __float2bfloat16(v);
    }
}

// ---------------------------------------------------------------------------
// kgemm: T = Zbf @ B^T via mma.sync bf16. grid (512, 14), 256 threads.
//   CTA tile 128(M) x 128(N), K=256 smem-resident. Warp tile 32x64.
// ---------------------------------------------------------------------------
#define RSTRIDE 528   // bytes per smem row (256 bf16 = 512 + 16 pad)

extern "C" __global__ void __launch_bounds__(256, 1)
kgemm() {
    extern __shared__ char smem[];
    uint32_t sb = smem_u32(smem);
    const uint32_t As = sb, Bs = sb + 128 * RSTRIDE;
    int tid = threadIdx.x, lane = tid & 31, w = tid >> 5;
    int wm = w >> 1, wn = w & 1;
    int mtile = blockIdx.x, nt = blockIdx.y;

    // stage A and B tiles (16B chunks, padded rows)
    const uint4* asrc = (const uint4*)(g_zbf + (size_t)mtile * 128 * 256);
    const uint4* bsrc = (const uint4*)(g_Bg + (size_t)nt * 128 * 256);
#pragma unroll
    for (int i = 0; i < 16; i++) {
        int f = tid + i * 256;            // 4096 chunks
        int row = f >> 5, c = f & 31;
        *(uint4*)(smem + row * RSTRIDE + c * 16) = asrc[f];
        *(uint4*)(smem + 128 * RSTRIDE + row * RSTRIDE + c * 16) = bsrc[f];
    }
    __syncthreads();

    float acc[2][8][4];
#pragma unroll
    for (int mi = 0; mi < 2; mi++)
#pragma unroll
        for (int nf = 0; nf < 8; nf++)
#pragma unroll
            for (int r = 0; r < 4; r++) acc[mi][nf][r] = 0.f;

    int lrow = lane & 15, lhi = lane >> 4;
#pragma unroll
    for (int ks = 0; ks < 16; ks++) {
        uint32_t coff = ks * 32 + lhi * 16;
        uint32_t a[2][4], b[4][4];
#pragma unroll
        for (int mi = 0; mi < 2; mi++) {
            uint32_t ad = As + (wm * 32 + mi * 16 + lrow) * RSTRIDE + coff;
            LDMX4(a[mi][0], a[mi][1], a[mi][2], a[mi][3], ad);
        }
#pragma unroll
        for (int bi = 0; bi < 4; bi++) {
            uint32_t bd = Bs + (wn * 64 + bi * 16 + lrow) * RSTRIDE + coff;
            LDMX4(b[bi][0], b[bi][1], b[bi][2], b[bi][3], bd);
        }
#pragma unroll
        for (int mi = 0; mi < 2; mi++)
#pragma unroll
            for (int bi = 0; bi < 4; bi++) {
                uint32_t blo[2] = { b[bi][0], b[bi][2] };
                uint32_t bhi[2] = { b[bi][1], b[bi][3] };
                MMA16816(acc[mi][bi * 2 + 0], a[mi], blo);
                MMA16816(acc[mi][bi * 2 + 1], a[mi], bhi);
            }
    }

    // ---- epilogue ----
    if (nt < 8) {
        // phi_mem: relu^2 reduce. warp's 32 rows lie in one batch half.
        float rsum = 0.f;
#pragma unroll
        for (int mi = 0; mi < 2; mi++)
#pragma unroll
            for (int nf = 0; nf < 8; nf++)
#pragma unroll
                for (int r = 0; r < 4; r++) {
                    float v = fmaxf(acc[mi][nf][r], 0.f);
                    rsum += v * v;
                }
#pragma unroll
        for (int o = 16; o > 0; o >>= 1) rsum += __shfl_xor_sync(0xffffffffu, rsum, o);
        __shared__ float red[8];
        if (lane == 0) red[w] = rsum;
        __syncthreads();
        if (tid == 0)
            g_memsum[(size_t)(mtile * 2 + 0) * 8 + nt] = red[0] + red[1] + red[2] + red[3];
        if (tid == 128)
            g_memsum[(size_t)(mtile * 2 + 1) * 8 + nt] = red[4] + red[5] + red[6] + red[7];
    } else {
        float* gout;
        int tc;
        if (nt < 10)      { gout = g_q;   tc = nt - 8; }
        else if (nt < 12) { gout = g_k;   tc = nt - 10; }
        else              { gout = g_enc; tc = nt - 12; }
        int colbase = tc * 128 + wn * 64 + (lane & 3) * 2;
        int rowbase = mtile * 128 + wm * 32 + (lane >> 2);
#pragma unroll
        for (int mi = 0; mi < 2; mi++)
#pragma unroll
            for (int nf = 0; nf < 8; nf++) {
                int col = colbase + nf * 8;
                int r0 = rowbase + mi * 16;
                float2 v0 = make_float2(acc[mi][nf][0], acc[mi][nf][1]);
                float2 v1 = make_float2(acc[mi][nf][2], acc[mi][nf][3]);
                *(float2*)(gout + (size_t)r0 * 256 + col) = v0;
                *(float2*)(gout + (size_t)(r0 + 8) * 256 + col) = v1;
            }
    }
}

// ---------------------------------------------------------------------------
// kzlite: out[b] = quad_z - phi_bias - phi_pos
// ---------------------------------------------------------------------------
extern "C" __global__ void __launch_bounds__(256)
kzlite(const float* __restrict__ z, const float* __restrict__ eb,
       const float* __restrict__ pos, float* __restrict__ out) {
    __shared__ float red[8];
    int b = blockIdx.x, tid = threadIdx.x;
    const float4* z4 = (const float4*)(z + (size_t)b * 16384);
    const float4* p4 = (const float4*)pos;
    float acc = 0.f;
#pragma unroll
    for (int i = 0; i < 16; i++) {
        int f = tid + i * 256;
        float4 zv = z4[f];
        int d = (f * 4) & 255;
        float4 ev = *(const float4*)(eb + d);
        float4 pv = p4[f];
        acc += 0.5f * (zv.x * zv.x + zv.y * zv.y + zv.z * zv.z + zv.w * zv.w)
             - (zv.x * ev.x + zv.y * ev.y + zv.z * ev.z + zv.w * ev.w)
             - (zv.x * pv.x + zv.y * pv.y + zv.z * pv.z + zv.w * pv.w);
    }
    float tot = block_reduce_256(acc, red);
    if (tid == 0) out[b] = tot;
}

// ---------------------------------------------------------------------------
// kalite: out[b] -= phi_att from Q,K scratch
// ---------------------------------------------------------------------------
extern "C" __global__ void __launch_bounds__(256)
kalite(float* __restrict__ out) {
    extern __shared__ float sm[];
    float* qs = sm;              // 64 x 260
    float* ks = qs + 64 * 260;
    float* red = ks + 64 * 260;  // 8

    int b = blockIdx.x, tid = threadIdx.x;
    const float4* qsrc = (const float4*)(g_q + (size_t)b * 64 * 256);
    const float4* ksrc = (const float4*)(g_k + (size_t)b * 64 * 256);
#pragma unroll
    for (int i = 0; i < 16; i++) {
        int f = tid + i * 256;
        int p = f >> 6, d = (f & 63) * 4;
        *(float4*)&qs[p * 260 + d] = qsrc[f];
        *(float4*)&ks[p * 260 + d] = ksrc[f];
    }
    __syncthreads();

    int m = tid >> 2, nq = tid & 3;
    float att = 0.f;
    for (int h = 0; h < 8; h++) {
        float qreg[32];
#pragma unroll
        for (int r4 = 0; r4 < 8; r4++) {
            float4 v = *(const float4*)&qs[m * 260 + h * 32 + r4 * 4];
            qreg[r4 * 4 + 0] = v.x; qreg[r4 * 4 + 1] = v.y;
            qreg[r4 * 4 + 2] = v.z; qreg[r4 * 4 + 3] = v.w;
        }
        float a[16];
#pragma unroll
        for (int nn = 0; nn < 16; nn++) {
            int n = nq + nn * 4;
            float s = 0.f;
#pragma unroll
            for (int r4 = 0; r4 < 8; r4++) {
                float4 kv = *(const float4*)&ks[n * 260 + h * 32 + r4 * 4];
                s += qreg[r4 * 4 + 0] * kv.x + qreg[r4 * 4 + 1] * kv.y +
                     qreg[r4 * 4 + 2] * kv.z + qreg[r4 * 4 + 3] * kv.w;
            }
            a[nn] = s;
        }
        float amax = a[0];
#pragma unroll
        for (int nn = 1; nn < 16; nn++) amax = fmaxf(amax, a[nn]);
        amax = fmaxf(amax, __shfl_xor_sync(0xffffffffu, amax, 1));
        amax = fmaxf(amax, __shfl_xor_sync(0xffffffffu, amax, 2));
        float se = 0.f;
#pragma unroll
        for (int nn = 0; nn < 16; nn++) se += __expf(GAMMA * (a[nn] - amax));
        se += __shfl_xor_sync(0xffffffffu, se, 1);
        se += __shfl_xor_sync(0xffffffffu, se, 2);
        if (nq == 0) att += amax + __logf(se) * (1.f / GAMMA);
    }
    float tot = block_reduce_256(att, red);
    if (tid == 0) out[b] -= tot;
}

// ---------------------------------------------------------------------------
// kxlite: out[b] += quad_x - phi_vis - phi_enc - phi_mem
// ---------------------------------------------------------------------------
extern "C" __global__ void __launch_bounds__(256)
kxlite(const float* __restrict__ x, const float* __restrict__ vb,
       float* __restrict__ out) {
    __shared__ float red[8];
    int b = blockIdx.x, tid = threadIdx.x;
    const float* xb = x + (size_t)b * 12288;
    const float* tb = g_enc + (size_t)b * 64 * 256;
    float local = 0.f;
    for (int idx = tid; idx < 12288; idx += 256) {
        float xv = xb[idx], v = vb[idx];
        int c = idx >> 12, rem = idx & 4095, ii = rem >> 6, jj = rem & 63;
        int p = ((ii >> 3) << 3) + (jj >> 3);
        int k = (c << 6) + ((ii & 7) << 3) + (jj & 7);
        local += xv * (0.5f * xv - v - tb[p * 256 + k]);
    }
    float tot = block_reduce_256(local, red);
    if (tid == 0) {
        const float* ms = g_memsum + (size_t)b * 8;
        float msum = ms[0] + ms[1] + ms[2] + ms[3] + ms[4] + ms[5] + ms[6] + ms[7];
        out[b] += tot - msum;
    }
}

// ---------------------------------------------------------------------------
extern "C" void kernel_launch(void* const* d_in, const int* in_sizes, int n_in,
                              void* d_out, int out_size) {
    (void)in_sizes; (void)n_in; (void)out_size;
    const float* x   = (const float*)d_in[0];
    const float* z   = (const float*)d_in[1];
    const float* We  = (const float*)d_in[2];
    const float* ebv = (const float*)d_in[3];
    const float* vb  = (const float*)d_in[4];
    const float* pos = (const float*)d_in[5];
    const float* Wm  = (const float*)d_in[6];
    const float* WQ  = (const float*)d_in[7];
    const float* WK  = (const float*)d_in[8];
    float* out = (float*)d_out;

    size_t shg = (size_t)2 * 128 * RSTRIDE;                    // 135168 B
    size_t sha = (size_t)(2 * 64 * 260 + 8) * sizeof(float);   // ~133 KB

    cudaFuncSetAttribute(kgemm,  cudaFuncAttributeMaxDynamicSharedMemorySize, (int)shg);
    cudaFuncSetAttribute(kalite, cudaFuncAttributeMaxDynamicSharedMemorySize, (int)sha);

    kprepA<<<8192, 256>>>(z);
    kprepB<<<dim3(14, 16), 256>>>(Wm, WQ, WK, We);
    kzlite<<<1024, 256>>>(z, ebv, pos, out);
    kgemm<<<dim3(512, 14), 256, shg>>>();
    kalite<<<1024, 256, sha>>>(out);
    kxlite<<<1024, 256>>>(x, vb, out);
}

// round 4
// speedup vs baseline: 9.9771x; 1.5135x over previous
#include <cuda_runtime.h>
#include <cuda_bf16.h>
#include <stdint.h>
#include <math.h>

#define GAMMA 0.25f
#define RSTRIDE 528              // smem row pitch bytes (256 bf16 + 16B pad)
#define ATILE  67584             // 128 * RSTRIDE
#define QSTR   528

// ---------------------------------------------------------------------------
// device scratch (static — no cudaMalloc allowed)
// ---------------------------------------------------------------------------
__device__ __align__(16) __nv_bfloat16 g_Bg[14 * 128 * 256];    // 14 B tiles [n][k]
__device__ __align__(16) __nv_bfloat16 g_qbf[65536 * 256];      // Q scratch bf16
__device__ __align__(16) __nv_bfloat16 g_kbf[65536 * 256];      // K scratch bf16
__device__ __align__(16) float g_enc[65536 * 256];              // enc scratch (cols<192 valid)

__device__ __forceinline__ uint32_t smem_u32(const void* p) {
    uint32_t a;
    asm("{ .reg .u64 t; cvta.to.shared.u64 t, %1; cvt.u32.u64 %0, t; }" : "=r"(a) : "l"(p));
    return a;
}

#define LDMX4(r0, r1, r2, r3, addr) \
    asm volatile("ldmatrix.sync.aligned.m8n8.x4.shared.b16 {%0,%1,%2,%3}, [%4];" \
                 : "=r"(r0), "=r"(r1), "=r"(r2), "=r"(r3) : "r"(addr))

#define MMA16816(d, a, b) \
    asm volatile("mma.sync.aligned.m16n8k16.row.col.f32.bf16.bf16.f32 " \
                 "{%0,%1,%2,%3}, {%4,%5,%6,%7}, {%8,%9}, {%0,%1,%2,%3};" \
                 : "+f"((d)[0]), "+f"((d)[1]), "+f"((d)[2]), "+f"((d)[3]) \
                 : "r"((a)[0]), "r"((a)[1]), "r"((a)[2]), "r"((a)[3]), \
                   "r"((b)[0]), "r"((b)[1]))

#define CPA16(dst, src) \
    asm volatile("cp.async.cg.shared.global [%0], [%1], 16;" :: "r"(dst), "l"(src) : "memory")
#define CPA_COMMIT() asm volatile("cp.async.commit_group;" ::: "memory")

// ---------------------------------------------------------------------------
__device__ __forceinline__ float block_reduce_256(float v, float* red) {
#pragma unroll
    for (int o = 16; o > 0; o >>= 1) v += __shfl_xor_sync(0xffffffffu, v, o);
    int w = threadIdx.x >> 5;
    if ((threadIdx.x & 31) == 0) red[w] = v;
    __syncthreads();
    if (threadIdx.x < 8) {
        v = red[threadIdx.x];
#pragma unroll
        for (int o = 4; o > 0; o >>= 1) v += __shfl_xor_sync(0x000000ffu, v, o);
    }
    return v;
}

// ---------------------------------------------------------------------------
// kprepB: build 14 dense bf16 B tiles [n][k]
// ---------------------------------------------------------------------------
extern "C" __global__ void __launch_bounds__(256)
kprepB(const float* __restrict__ Wm, const float* __restrict__ WQ,
       const float* __restrict__ WK, const float* __restrict__ We) {
    int nt = blockIdx.x;
    __nv_bfloat16* img = g_Bg + (size_t)nt * 128 * 256;
#pragma unroll
    for (int i = 0; i < 8; i++) {
        int f = (blockIdx.y * 256 + threadIdx.x) * 8 + i;   // grid.y = 16
        int n = f >> 8, k = f & 255;
        float v;
        if (nt < 8)        v = Wm[k * 1024 + nt * 128 + n];
        else if (nt < 10)  v = WQ[((nt - 8) * 128 + n) * 256 + k];
        else if (nt < 12)  v = WK[((nt - 10) * 128 + n) * 256 + k];
        else {
            int ng = (nt - 12) * 128 + n;
            v = (ng < 192) ? We[k * 192 + ng] : 0.f;
        }
        img[f] = __float2bfloat16(v);
    }
}

// ---------------------------------------------------------------------------
// kgemm: fused. grid 512, 256 threads.
//   A (z rows of 2 batch elems) resident in smem; loop 14 N-tiles with
//   cp.async double-buffered B. Fuses z->bf16, quad_z/bias/pos, phi_mem.
// ---------------------------------------------------------------------------
extern "C" __global__ void __launch_bounds__(256, 1)
kgemm(const float* __restrict__ z, const float* __restrict__ eb,
      const float* __restrict__ pos, float* __restrict__ out) {
    extern __shared__ char smem[];
    __shared__ float red[8], red2[8], mred[8];
    uint32_t sb = smem_u32(smem);
    const uint32_t As = sb;
    int tid = threadIdx.x, lane = tid & 31, w = tid >> 5;
    int wm = w >> 1, wn = w & 1;
    int mtile = blockIdx.x;

    // prefetch B tile 0 -> buf 0
    {
        const char* src = (const char*)(g_Bg);
#pragma unroll
        for (int i = 0; i < 16; i++) {
            int f = tid + i * 256;
            uint32_t dst = sb + ATILE + (f >> 5) * RSTRIDE + (f & 31) * 16;
            CPA16(dst, src + f * 16);
        }
        CPA_COMMIT();
    }

    // --- A load: z f32 -> bf16 smem + fused z statistics ---
    const float* zb = z + (size_t)mtile * 128 * 256;
    float zacc0 = 0.f, zacc1 = 0.f;
#pragma unroll
    for (int i = 0; i < 16; i++) {
        int f = tid + i * 256;               // chunk of 8 elems
        int row = f >> 5, c8 = (f & 31) * 8;
        const float4* zp = (const float4*)(zb + row * 256 + c8);
        float4 v0 = zp[0], v1 = zp[1];
        int prow = row & 63;
        float4 e0 = *(const float4*)(eb + c8);
        float4 e1 = *(const float4*)(eb + c8 + 4);
        float4 p0 = *(const float4*)(pos + prow * 256 + c8);
        float4 p1 = *(const float4*)(pos + prow * 256 + c8 + 4);
        float t =
            v0.x * (0.5f * v0.x - e0.x - p0.x) + v0.y * (0.5f * v0.y - e0.y - p0.y) +
            v0.z * (0.5f * v0.z - e0.z - p0.z) + v0.w * (0.5f * v0.w - e0.w - p0.w) +
            v1.x * (0.5f * v1.x - e1.x - p1.x) + v1.y * (0.5f * v1.y - e1.y - p1.y) +
            v1.z * (0.5f * v1.z - e1.z - p1.z) + v1.w * (0.5f * v1.w - e1.w - p1.w);
        if (i < 8) zacc0 += t; else zacc1 += t;
        uint4 pk;
        __nv_bfloat162 bt;
        bt = __floats2bfloat162_rn(v0.x, v0.y); pk.x = *(uint32_t*)&bt;
        bt = __floats2bfloat162_rn(v0.z, v0.w); pk.y = *(uint32_t*)&bt;
        bt = __floats2bfloat162_rn(v1.x, v1.y); pk.z = *(uint32_t*)&bt;
        bt = __floats2bfloat162_rn(v1.z, v1.w); pk.w = *(uint32_t*)&bt;
        *(uint4*)(smem + row * RSTRIDE + (f & 31) * 16) = pk;
    }

    // prefetch B tile 1 -> buf 1
    {
        const char* src = (const char*)(g_Bg + (size_t)128 * 256);
#pragma unroll
        for (int i = 0; i < 16; i++) {
            int f = tid + i * 256;
            uint32_t dst = sb + ATILE * 2 + (f >> 5) * RSTRIDE + (f & 31) * 16;
            CPA16(dst, src + f * 16);
        }
        CPA_COMMIT();
    }

    float msum = 0.f;
    int lrow = lane & 15, lhi = lane >> 4;

    for (int nt = 0; nt < 14; nt++) {
        uint32_t Bs = sb + ATILE + (uint32_t)(nt & 1) * ATILE;
        if (nt == 13) asm volatile("cp.async.wait_group 0;" ::: "memory");
        else          asm volatile("cp.async.wait_group 1;" ::: "memory");
        __syncthreads();

        float acc[2][8][4];
#pragma unroll
        for (int mi = 0; mi < 2; mi++)
#pragma unroll
            for (int nf = 0; nf < 8; nf++)
#pragma unroll
                for (int r = 0; r < 4; r++) acc[mi][nf][r] = 0.f;

#pragma unroll
        for (int ks = 0; ks < 16; ks++) {
            uint32_t coff = ks * 32 + lhi * 16;
            uint32_t a[2][4], b[4][4];
#pragma unroll
            for (int mi = 0; mi < 2; mi++) {
                uint32_t ad = As + (wm * 32 + mi * 16 + lrow) * RSTRIDE + coff;
                LDMX4(a[mi][0], a[mi][1], a[mi][2], a[mi][3], ad);
            }
#pragma unroll
            for (int bi = 0; bi < 4; bi++) {
                uint32_t bd = Bs + (wn * 64 + bi * 16 + lrow) * RSTRIDE + coff;
                LDMX4(b[bi][0], b[bi][1], b[bi][2], b[bi][3], bd);
            }
#pragma unroll
            for (int mi = 0; mi < 2; mi++)
#pragma unroll
                for (int bi = 0; bi < 4; bi++) {
                    uint32_t blo[2] = { b[bi][0], b[bi][2] };
                    uint32_t bhi[2] = { b[bi][1], b[bi][3] };
                    MMA16816(acc[mi][bi * 2 + 0], a[mi], blo);
                    MMA16816(acc[mi][bi * 2 + 1], a[mi], bhi);
                }
        }
        __syncthreads();   // all warps done reading buf (nt&1)

        // prefetch B[nt+2] into the buffer just freed
        if (nt + 2 < 14) {
            const char* src = (const char*)(g_Bg + (size_t)(nt + 2) * 128 * 256);
            uint32_t dstb = sb + ATILE + (uint32_t)(nt & 1) * ATILE;
#pragma unroll
            for (int i = 0; i < 16; i++) {
                int f = tid + i * 256;
                CPA16(dstb + (f >> 5) * RSTRIDE + (f & 31) * 16, src + f * 16);
            }
            CPA_COMMIT();
        }

        // ---- epilogue for this N-tile ----
        if (nt < 8) {
#pragma unroll
            for (int mi = 0; mi < 2; mi++)
#pragma unroll
                for (int nf = 0; nf < 8; nf++)
#pragma unroll
                    for (int r = 0; r < 4; r++) {
                        float v = fmaxf(acc[mi][nf][r], 0.f);
                        msum += v * v;
                    }
        } else if (nt < 12) {
            __nv_bfloat16* gout = (nt < 10) ? g_qbf : g_kbf;
            int tc = (nt < 10) ? (nt - 8) : (nt - 10);
            int colbase = tc * 128 + wn * 64 + (lane & 3) * 2;
            int rowbase = mtile * 128 + wm * 32 + (lane >> 2);
#pragma unroll
            for (int mi = 0; mi < 2; mi++)
#pragma unroll
                for (int nf = 0; nf < 8; nf++) {
                    int col = colbase + nf * 8;
                    int r0 = rowbase + mi * 16;
                    __nv_bfloat162 lo = __floats2bfloat162_rn(acc[mi][nf][0], acc[mi][nf][1]);
                    __nv_bfloat162 hi = __floats2bfloat162_rn(acc[mi][nf][2], acc[mi][nf][3]);
                    *(uint32_t*)(gout + (size_t)r0 * 256 + col) = *(uint32_t*)&lo;
                    *(uint32_t*)(gout + (size_t)(r0 + 8) * 256 + col) = *(uint32_t*)&hi;
                }
        } else {
            int tc = nt - 12;
            int colbase = tc * 128 + wn * 64 + (lane & 3) * 2;
            int rowbase = mtile * 128 + wm * 32 + (lane >> 2);
#pragma unroll
            for (int mi = 0; mi < 2; mi++)
#pragma unroll
                for (int nf = 0; nf < 8; nf++) {
                    int col = colbase + nf * 8;
                    int r0 = rowbase + mi * 16;
                    *(float2*)(g_enc + (size_t)r0 * 256 + col) =
                        make_float2(acc[mi][nf][0], acc[mi][nf][1]);
                    *(float2*)(g_enc + (size_t)(r0 + 8) * 256 + col) =
                        make_float2(acc[mi][nf][2], acc[mi][nf][3]);
                }
        }
    }

    // ---- final per-batch reductions: out[b] = zterms - phi_mem ----
#pragma unroll
    for (int o = 16; o > 0; o >>= 1) msum += __shfl_xor_sync(0xffffffffu, msum, o);
    if (lane == 0) mred[w] = msum;
    float t0 = block_reduce_256(zacc0, red);
    float t1 = block_reduce_256(zacc1, red2);
    __syncthreads();
    if (tid == 0) {
        out[2 * mtile]     = t0 - (mred[0] + mred[1] + mred[2] + mred[3]);
        out[2 * mtile + 1] = t1 - (mred[4] + mred[5] + mred[6] + mred[7]);
    }
}

// ---------------------------------------------------------------------------
// kalite: out[b] -= phi_att. Logits via mma.sync from bf16 Q,K scratch.
//   Block = batch b, warp w = head h. 64x64 logits per head, K-dim = 32.
// ---------------------------------------------------------------------------
extern "C" __global__ void __launch_bounds__(256)
kalite(float* __restrict__ out) {
    extern __shared__ char sm[];
    __shared__ float red[8];
    uint32_t sb = smem_u32(sm);
    uint32_t Qs = sb, Ks = sb + 64 * QSTR;
    int b = blockIdx.x, tid = threadIdx.x, lane = tid & 31, h = tid >> 5;

    const uint4* qsrc = (const uint4*)(g_qbf + (size_t)b * 64 * 256);
    const uint4* ksrc = (const uint4*)(g_kbf + (size_t)b * 64 * 256);
#pragma unroll
    for (int i = 0; i < 8; i++) {
        int c = tid + i * 256;               // 2048 chunks each
        int row = c >> 5, cc = (c & 31) * 16;
        *(uint4*)(sm + row * QSTR + cc) = qsrc[c];
        *(uint4*)(sm + 64 * QSTR + row * QSTR + cc) = ksrc[c];
    }
    __syncthreads();

    int lrow = lane & 15, lhi = lane >> 4;
    float acc[4][8][4];
#pragma unroll
    for (int mf = 0; mf < 4; mf++)
#pragma unroll
        for (int nf = 0; nf < 8; nf++)
#pragma unroll
            for (int r = 0; r < 4; r++) acc[mf][nf][r] = 0.f;

#pragma unroll
    for (int kc = 0; kc < 2; kc++) {
        uint32_t coff = h * 64 + kc * 32 + lhi * 16;
        uint32_t a[4][4], bb[4][4];
#pragma unroll
        for (int mf = 0; mf < 4; mf++)
            LDMX4(a[mf][0], a[mf][1], a[mf][2], a[mf][3],
                  Qs + (mf * 16 + lrow) * QSTR + coff);
#pragma unroll
        for (int bi = 0; bi < 4; bi++)
            LDMX4(bb[bi][0], bb[bi][1], bb[bi][2], bb[bi][3],
                  Ks + (bi * 16 + lrow) * QSTR + coff);
#pragma unroll
        for (int mf = 0; mf < 4; mf++)
#pragma unroll
            for (int bi = 0; bi < 4; bi++) {
                uint32_t blo[2] = { bb[bi][0], bb[bi][2] };
                uint32_t bhi[2] = { bb[bi][1], bb[bi][3] };
                MMA16816(acc[mf][bi * 2 + 0], a[mf], blo);
                MMA16816(acc[mf][bi * 2 + 1], a[mf], bhi);
            }
    }

    // row-wise LSE: each (mf, rl) row held by quad (lane&3), 16 vals/thread
    float att = 0.f;
#pragma unroll
    for (int mf = 0; mf < 4; mf++)
#pragma unroll
        for (int rl = 0; rl < 2; rl++) {
            float amax = -1e30f;
#pragma unroll
            for (int nf = 0; nf < 8; nf++) {
                amax = fmaxf(amax, acc[mf][nf][rl * 2 + 0]);
                amax = fmaxf(amax, acc[mf][nf][rl * 2 + 1]);
            }
            amax = fmaxf(amax, __shfl_xor_sync(0xffffffffu, amax, 1));
            amax = fmaxf(amax, __shfl_xor_sync(0xffffffffu, amax, 2));
            float se = 0.f;
#pragma unroll
            for (int nf = 0; nf < 8; nf++) {
                se += __expf(GAMMA * (acc[mf][nf][rl * 2 + 0] - amax));
                se += __expf(GAMMA * (acc[mf][nf][rl * 2 + 1] - amax));
            }
            se += __shfl_xor_sync(0xffffffffu, se, 1);
            se += __shfl_xor_sync(0xffffffffu, se, 2);
            if ((lane & 3) == 0) att += amax + __logf(se) * (1.f / GAMMA);
        }

    float tot = block_reduce_256(att, red);
    if (tid == 0) out[b] -= tot;
}

// ---------------------------------------------------------------------------
// kxlite: out[b] += quad_x - phi_vis - phi_enc
// ---------------------------------------------------------------------------
extern "C" __global__ void __launch_bounds__(256)
kxlite(const float* __restrict__ x, const float* __restrict__ vb,
       float* __restrict__ out) {
    __shared__ float red[8];
    int b = blockIdx.x, tid = threadIdx.x;
    const float* xb = x + (size_t)b * 12288;
    const float* tb = g_enc + (size_t)b * 64 * 256;
    float local = 0.f;
    for (int idx = tid; idx < 12288; idx += 256) {
        float xv = xb[idx], v = vb[idx];
        int c = idx >> 12, rem = idx & 4095, ii = rem >> 6, jj = rem & 63;
        int p = ((ii >> 3) << 3) + (jj >> 3);
        int k = (c << 6) + ((ii & 7) << 3) + (jj & 7);
        local += xv * (0.5f * xv - v - tb[p * 256 + k]);
    }
    float tot = block_reduce_256(local, red);
    if (tid == 0) out[b] += tot;
}

// ---------------------------------------------------------------------------
extern "C" void kernel_launch(void* const* d_in, const int* in_sizes, int n_in,
                              void* d_out, int out_size) {
    (void)in_sizes; (void)n_in; (void)out_size;
    const float* x   = (const float*)d_in[0];
    const float* z   = (const float*)d_in[1];
    const float* We  = (const float*)d_in[2];
    const float* ebv = (const float*)d_in[3];
    const float* vb  = (const float*)d_in[4];
    const float* pos = (const float*)d_in[5];
    const float* Wm  = (const float*)d_in[6];
    const float* WQ  = (const float*)d_in[7];
    const float* WK  = (const float*)d_in[8];
    float* out = (float*)d_out;

    size_t shg = (size_t)3 * ATILE;      // 202752 B
    size_t sha = (size_t)2 * 64 * QSTR;  // 67584 B

    cudaFuncSetAttribute(kgemm,  cudaFuncAttributeMaxDynamicSharedMemorySize, (int)shg);
    cudaFuncSetAttribute(kalite, cudaFuncAttributeMaxDynamicSharedMemorySize, (int)sha);

    kprepB<<<dim3(14, 16), 256>>>(Wm, WQ, WK, We);
    kgemm<<<512, 256, shg>>>(z, ebv, pos, out);
    kalite<<<1024, 256, sha>>>(out);
    kxlite<<<1024, 256>>>(x, vb, out);
}

// round 6
// speedup vs baseline: 11.2542x; 1.1280x over previous
#include <cuda_runtime.h>
#include <cuda_bf16.h>
#include <stdint.h>
#include <math.h>

#define GAMMA 0.25f
#define RSTRIDE 528              // smem row pitch bytes (256 bf16 + 16B pad)
#define ATILE  67584             // 128 * RSTRIDE
#define QSTR   528

// ---------------------------------------------------------------------------
// device scratch (static — no cudaMalloc allowed)
// ---------------------------------------------------------------------------
__device__ __align__(16) __nv_bfloat16 g_Bg[14 * 128 * 256];    // 14 B tiles [n][k]
__device__ __align__(16) __nv_bfloat16 g_qbf[65536 * 256];      // Q scratch bf16
__device__ __align__(16) __nv_bfloat16 g_kbf[65536 * 256];      // K scratch bf16

__device__ __forceinline__ uint32_t smem_u32(const void* p) {
    uint32_t a;
    asm("{ .reg .u64 t; cvta.to.shared.u64 t, %1; cvt.u32.u64 %0, t; }" : "=r"(a) : "l"(p));
    return a;
}

#define LDMX4(r0, r1, r2, r3, addr) \
    asm volatile("ldmatrix.sync.aligned.m8n8.x4.shared.b16 {%0,%1,%2,%3}, [%4];" \
                 : "=r"(r0), "=r"(r1), "=r"(r2), "=r"(r3) : "r"(addr))

#define MMA16816(d, a, b) \
    asm volatile("mma.sync.aligned.m16n8k16.row.col.f32.bf16.bf16.f32 " \
                 "{%0,%1,%2,%3}, {%4,%5,%6,%7}, {%8,%9}, {%0,%1,%2,%3};" \
                 : "+f"((d)[0]), "+f"((d)[1]), "+f"((d)[2]), "+f"((d)[3]) \
                 : "r"((a)[0]), "r"((a)[1]), "r"((a)[2]), "r"((a)[3]), \
                   "r"((b)[0]), "r"((b)[1]))

#define CPA16(dst, src) \
    asm volatile("cp.async.cg.shared.global [%0], [%1], 16;" :: "r"(dst), "l"(src) : "memory")
#define CPA_COMMIT() asm volatile("cp.async.commit_group;" ::: "memory")

// ---------------------------------------------------------------------------
__device__ __forceinline__ float block_reduce_256(float v, float* red) {
#pragma unroll
    for (int o = 16; o > 0; o >>= 1) v += __shfl_xor_sync(0xffffffffu, v, o);
    int w = threadIdx.x >> 5;
    if ((threadIdx.x & 31) == 0) red[w] = v;
    __syncthreads();
    if (threadIdx.x < 8) {
        v = red[threadIdx.x];
#pragma unroll
        for (int o = 4; o > 0; o >>= 1) v += __shfl_xor_sync(0x000000ffu, v, o);
    }
    return v;
}

// ---------------------------------------------------------------------------
// kprepB: build 14 dense bf16 B tiles [n][k]
// ---------------------------------------------------------------------------
extern "C" __global__ void __launch_bounds__(256)
kprepB(const float* __restrict__ Wm, const float* __restrict__ WQ,
       const float* __restrict__ WK, const float* __restrict__ We) {
    int nt = blockIdx.x;
    __nv_bfloat16* img = g_Bg + (size_t)nt * 128 * 256;
#pragma unroll
    for (int i = 0; i < 8; i++) {
        int f = (blockIdx.y * 256 + threadIdx.x) * 8 + i;   // grid.y = 16
        int n = f >> 8, k = f & 255;
        float v;
        if (nt < 8)        v = Wm[k * 1024 + nt * 128 + n];
        else if (nt < 10)  v = WQ[((nt - 8) * 128 + n) * 256 + k];
        else if (nt < 12)  v = WK[((nt - 10) * 128 + n) * 256 + k];
        else {
            int ng = (nt - 12) * 128 + n;
            v = (ng < 192) ? We[k * 192 + ng] : 0.f;
        }
        img[f] = __float2bfloat16(v);
    }
}

// ---------------------------------------------------------------------------
// kgemm: fused. grid 512, 256 threads.
//   A (z rows of 2 batch elems) resident in smem; loop 14 N-tiles with
//   cp.async double-buffered B. Fuses: z->bf16, quad_z/bias/pos, phi_mem,
//   and (new) the entire x-side: quad_x - phi_vis - phi_enc read straight
//   off the nt=12/13 MMA accumulators with coalesced x/vb loads.
//   out[b] = everything except phi_att.
// ---------------------------------------------------------------------------
extern "C" __global__ void __launch_bounds__(256, 1)
kgemm(const float* __restrict__ x, const float* __restrict__ z,
      const float* __restrict__ eb, const float* __restrict__ pos,
      const float* __restrict__ vb, float* __restrict__ out) {
    extern __shared__ char smem[];
    __shared__ float red[8], red2[8], mred[8];
    uint32_t sb = smem_u32(smem);
    const uint32_t As = sb;
    int tid = threadIdx.x, lane = tid & 31, w = tid >> 5;
    int wm = w >> 1, wn = w & 1;
    int mtile = blockIdx.x;

    // prefetch B tile 0 -> buf 0
    {
        const char* src = (const char*)(g_Bg);
#pragma unroll
        for (int i = 0; i < 16; i++) {
            int f = tid + i * 256;
            uint32_t dst = sb + ATILE + (f >> 5) * RSTRIDE + (f & 31) * 16;
            CPA16(dst, src + f * 16);
        }
        CPA_COMMIT();
    }

    // --- A load: z f32 -> bf16 smem + fused z statistics ---
    const float* zb = z + (size_t)mtile * 128 * 256;
    float zacc0 = 0.f, zacc1 = 0.f;
#pragma unroll
    for (int i = 0; i < 16; i++) {
        int f = tid + i * 256;               // chunk of 8 elems
        int row = f >> 5, c8 = (f & 31) * 8;
        const float4* zp = (const float4*)(zb + row * 256 + c8);
        float4 v0 = zp[0], v1 = zp[1];
        int prow = row & 63;
        float4 e0 = *(const float4*)(eb + c8);
        float4 e1 = *(const float4*)(eb + c8 + 4);
        float4 p0 = *(const float4*)(pos + prow * 256 + c8);
        float4 p1 = *(const float4*)(pos + prow * 256 + c8 + 4);
        float t =
            v0.x * (0.5f * v0.x - e0.x - p0.x) + v0.y * (0.5f * v0.y - e0.y - p0.y) +
            v0.z * (0.5f * v0.z - e0.z - p0.z) + v0.w * (0.5f * v0.w - e0.w - p0.w) +
            v1.x * (0.5f * v1.x - e1.x - p1.x) + v1.y * (0.5f * v1.y - e1.y - p1.y) +
            v1.z * (0.5f * v1.z - e1.z - p1.z) + v1.w * (0.5f * v1.w - e1.w - p1.w);
        if (i < 8) zacc0 += t; else zacc1 += t;
        uint4 pk;
        __nv_bfloat162 bt;
        bt = __floats2bfloat162_rn(v0.x, v0.y); pk.x = *(uint32_t*)&bt;
        bt = __floats2bfloat162_rn(v0.z, v0.w); pk.y = *(uint32_t*)&bt;
        bt = __floats2bfloat162_rn(v1.x, v1.y); pk.z = *(uint32_t*)&bt;
        bt = __floats2bfloat162_rn(v1.z, v1.w); pk.w = *(uint32_t*)&bt;
        *(uint4*)(smem + row * RSTRIDE + (f & 31) * 16) = pk;
    }

    // prefetch B tile 1 -> buf 1
    {
        const char* src = (const char*)(g_Bg + (size_t)128 * 256);
#pragma unroll
        for (int i = 0; i < 16; i++) {
            int f = tid + i * 256;
            uint32_t dst = sb + ATILE * 2 + (f >> 5) * RSTRIDE + (f & 31) * 16;
            CPA16(dst, src + f * 16);
        }
        CPA_COMMIT();
    }

    float msum = 0.f;          // phi_mem (subtract)
    float xsum = 0.f;          // quad_x - phi_vis - phi_enc (add)
    const float* xb = x + (size_t)mtile * 2 * 12288;
    int lrow = lane & 15, lhi = lane >> 4;

    for (int nt = 0; nt < 14; nt++) {
        uint32_t Bs = sb + ATILE + (uint32_t)(nt & 1) * ATILE;
        if (nt == 13) asm volatile("cp.async.wait_group 0;" ::: "memory");
        else          asm volatile("cp.async.wait_group 1;" ::: "memory");
        __syncthreads();

        float acc[2][8][4];
#pragma unroll
        for (int mi = 0; mi < 2; mi++)
#pragma unroll
            for (int nf = 0; nf < 8; nf++)
#pragma unroll
                for (int r = 0; r < 4; r++) acc[mi][nf][r] = 0.f;

#pragma unroll
        for (int ks = 0; ks < 16; ks++) {
            uint32_t coff = ks * 32 + lhi * 16;
            uint32_t a[2][4], b[4][4];
#pragma unroll
            for (int mi = 0; mi < 2; mi++) {
                uint32_t ad = As + (wm * 32 + mi * 16 + lrow) * RSTRIDE + coff;
                LDMX4(a[mi][0], a[mi][1], a[mi][2], a[mi][3], ad);
            }
#pragma unroll
            for (int bi = 0; bi < 4; bi++) {
                uint32_t bd = Bs + (wn * 64 + bi * 16 + lrow) * RSTRIDE + coff;
                LDMX4(b[bi][0], b[bi][1], b[bi][2], b[bi][3], bd);
            }
#pragma unroll
            for (int mi = 0; mi < 2; mi++)
#pragma unroll
                for (int bi = 0; bi < 4; bi++) {
                    uint32_t blo[2] = { b[bi][0], b[bi][2] };
                    uint32_t bhi[2] = { b[bi][1], b[bi][3] };
                    MMA16816(acc[mi][bi * 2 + 0], a[mi], blo);
                    MMA16816(acc[mi][bi * 2 + 1], a[mi], bhi);
                }
        }
        __syncthreads();   // all warps done reading buf (nt&1)

        // prefetch B[nt+2] into the buffer just freed
        if (nt + 2 < 14) {
            const char* src = (const char*)(g_Bg + (size_t)(nt + 2) * 128 * 256);
            uint32_t dstb = sb + ATILE + (uint32_t)(nt & 1) * ATILE;
#pragma unroll
            for (int i = 0; i < 16; i++) {
                int f = tid + i * 256;
                CPA16(dstb + (f >> 5) * RSTRIDE + (f & 31) * 16, src + f * 16);
            }
            CPA_COMMIT();
        }

        // ---- epilogue for this N-tile ----
        if (nt < 8) {
            // phi_mem: relu^2 reduce in-register
#pragma unroll
            for (int mi = 0; mi < 2; mi++)
#pragma unroll
                for (int nf = 0; nf < 8; nf++)
#pragma unroll
                    for (int r = 0; r < 4; r++) {
                        float v = fmaxf(acc[mi][nf][r], 0.f);
                        msum += v * v;
                    }
        } else if (nt < 12) {
            __nv_bfloat16* gout = (nt < 10) ? g_qbf : g_kbf;
            int tc = (nt < 10) ? (nt - 8) : (nt - 10);
            int colbase = tc * 128 + wn * 64 + (lane & 3) * 2;
            int rowbase = mtile * 128 + wm * 32 + (lane >> 2);
#pragma unroll
            for (int mi = 0; mi < 2; mi++)
#pragma unroll
                for (int nf = 0; nf < 8; nf++) {
                    int col = colbase + nf * 8;
                    int r0 = rowbase + mi * 16;
                    __nv_bfloat162 lo = __floats2bfloat162_rn(acc[mi][nf][0], acc[mi][nf][1]);
                    __nv_bfloat162 hi = __floats2bfloat162_rn(acc[mi][nf][2], acc[mi][nf][3]);
                    *(uint32_t*)(gout + (size_t)r0 * 256 + col) = *(uint32_t*)&lo;
                    *(uint32_t*)(gout + (size_t)(r0 + 8) * 256 + col) = *(uint32_t*)&hi;
                }
        } else {
            // enc tiles: consume accumulators directly against x (coalesced).
            // k = (nt-12)*128 + wn*64 + nf*8 + (lane&3)*2 + r  (valid k<192)
            int tc = nt - 12;
            if (!(tc == 1 && wn == 1)) {           // those cols are k>=192 (pad)
                int c = tc * 2 + wn;               // channel = k>>6
#pragma unroll
                for (int mi = 0; mi < 2; mi++)
#pragma unroll
                    for (int rp = 0; rp < 2; rp++) {
                        int l = wm * 32 + mi * 16 + rp * 8 + (lane >> 2);  // local row
                        int p = l & 63;
                        int jj = (p & 7) * 8 + (lane & 3) * 2;
                        size_t base0 = (size_t)(l >> 6) * 12288 + c * 4096 + (p >> 3) * 8 * 64 + jj;
#pragma unroll
                        for (int nf = 0; nf < 8; nf++) {
                            size_t off = base0 + nf * 64;  // ii = (p>>3)*8 + nf
                            float2 xv = *(const float2*)(xb + off);
                            float2 vv = *(const float2*)(vb + (off - (size_t)(l >> 6) * 12288));
                            float a0 = acc[mi][nf][rp * 2 + 0];
                            float a1 = acc[mi][nf][rp * 2 + 1];
                            xsum += xv.x * (0.5f * xv.x - vv.x - a0)
                                  + xv.y * (0.5f * xv.y - vv.y - a1);
                        }
                    }
            }
        }
    }

    // ---- final per-batch reductions: out[b] = zterms + xterms - phi_mem ----
    float wsum = xsum - msum;          // this thread's batch = wm>>1
#pragma unroll
    for (int o = 16; o > 0; o >>= 1) wsum += __shfl_xor_sync(0xffffffffu, wsum, o);
    if (lane == 0) mred[w] = wsum;
    float t0 = block_reduce_256(zacc0, red);
    float t1 = block_reduce_256(zacc1, red2);
    __syncthreads();
    if (tid == 0) {
        out[2 * mtile]     = t0 + (mred[0] + mred[1] + mred[2] + mred[3]);
        out[2 * mtile + 1] = t1 + (mred[4] + mred[5] + mred[6] + mred[7]);
    }
}

// ---------------------------------------------------------------------------
// kalite: out[b] -= phi_att. Logits via mma.sync from bf16 Q,K scratch.
//   Block = batch b; warp w = head w, two 32-row tasks sequentially
//   (halves acc registers -> 2 CTAs/SM).
// ---------------------------------------------------------------------------
extern "C" __global__ void __launch_bounds__(256, 2)
kalite(float* __restrict__ out) {
    extern __shared__ char sm[];
    __shared__ float red[8];
    uint32_t sb = smem_u32(sm);
    uint32_t Qs = sb, Ks = sb + 64 * QSTR;
    int b = blockIdx.x, tid = threadIdx.x, lane = tid & 31, w = tid >> 5;

    const uint4* qsrc = (const uint4*)(g_qbf + (size_t)b * 64 * 256);
    const uint4* ksrc = (const uint4*)(g_kbf + (size_t)b * 64 * 256);
#pragma unroll
    for (int i = 0; i < 8; i++) {
        int c = tid + i * 256;               // 2048 chunks each
        int row = c >> 5, cc = (c & 31) * 16;
        *(uint4*)(sm + row * QSTR + cc) = qsrc[c];
        *(uint4*)(sm + 64 * QSTR + row * QSTR + cc) = ksrc[c];
    }
    __syncthreads();

    int lrow = lane & 15, lhi = lane >> 4;
    float att = 0.f;

#pragma unroll
    for (int it = 0; it < 2; it++) {         // row-half of this head's 64 rows
        float acc[2][8][4];
#pragma unroll
        for (int mf = 0; mf < 2; mf++)
#pragma unroll
            for (int nf = 0; nf < 8; nf++)
#pragma unroll
                for (int r = 0; r < 4; r++) acc[mf][nf][r] = 0.f;

#pragma unroll
        for (int kc = 0; kc < 2; kc++) {
            uint32_t coff = w * 64 + kc * 32 + lhi * 16;
            uint32_t a[2][4], bb[4][4];
#pragma unroll
            for (int mf = 0; mf < 2; mf++)
                LDMX4(a[mf][0], a[mf][1], a[mf][2], a[mf][3],
                      Qs + (it * 32 + mf * 16 + lrow) * QSTR + coff);
#pragma unroll
            for (int bi = 0; bi < 4; bi++)
                LDMX4(bb[bi][0], bb[bi][1], bb[bi][2], bb[bi][3],
                      Ks + (bi * 16 + lrow) * QSTR + coff);
#pragma unroll
            for (int mf = 0; mf < 2; mf++)
#pragma unroll
                for (int bi = 0; bi < 4; bi++) {
                    uint32_t blo[2] = { bb[bi][0], bb[bi][2] };
                    uint32_t bhi[2] = { bb[bi][1], bb[bi][3] };
                    MMA16816(acc[mf][bi * 2 + 0], a[mf], blo);
                    MMA16816(acc[mf][bi * 2 + 1], a[mf], bhi);
                }
        }

        // row-wise LSE: each (mf, rl) row held by quad (lane&3)
#pragma unroll
        for (int mf = 0; mf < 2; mf++)
#pragma unroll
            for (int rl = 0; rl < 2; rl++) {
                float amax = -1e30f;
#pragma unroll
                for (int nf = 0; nf < 8; nf++) {
                    amax = fmaxf(amax, acc[mf][nf][rl * 2 + 0]);
                    amax = fmaxf(amax, acc[mf][nf][rl * 2 + 1]);
                }
                amax = fmaxf(amax, __shfl_xor_sync(0xffffffffu, amax, 1));
                amax = fmaxf(amax, __shfl_xor_sync(0xffffffffu, amax, 2));
                float se = 0.f;
#pragma unroll
                for (int nf = 0; nf < 8; nf++) {
                    se += __expf(GAMMA * (acc[mf][nf][rl * 2 + 0] - amax));
                    se += __expf(GAMMA * (acc[mf][nf][rl * 2 + 1] - amax));
                }
                se += __shfl_xor_sync(0xffffffffu, se, 1);
                se += __shfl_xor_sync(0xffffffffu, se, 2);
                if ((lane & 3) == 0) att += amax + __logf(se) * (1.f / GAMMA);
            }
    }

    float tot = block_reduce_256(att, red);
    if (tid == 0) out[b] -= tot;
}

// ---------------------------------------------------------------------------
extern "C" void kernel_launch(void* const* d_in, const int* in_sizes, int n_in,
                              void* d_out, int out_size) {
    (void)in_sizes; (void)n_in; (void)out_size;
    const float* x   = (const float*)d_in[0];
    const float* z   = (const float*)d_in[1];
    const float* We  = (const float*)d_in[2];
    const float* ebv = (const float*)d_in[3];
    const float* vb  = (const float*)d_in[4];
    const float* pos = (const float*)d_in[5];
    const float* Wm  = (const float*)d_in[6];
    const float* WQ  = (const float*)d_in[7];
    const float* WK  = (const float*)d_in[8];
    float* out = (float*)d_out;

    size_t shg = (size_t)3 * ATILE;      // 202752 B
    size_t sha = (size_t)2 * 64 * QSTR;  // 67584 B

    cudaFuncSetAttribute(kgemm,  cudaFuncAttributeMaxDynamicSharedMemorySize, (int)shg);
    cudaFuncSetAttribute(kalite, cudaFuncAttributeMaxDynamicSharedMemorySize, (int)sha);

    kprepB<<<dim3(14, 16), 256>>>(Wm, WQ, WK, We);
    kgemm<<<512, 256, shg>>>(x, z, ebv, pos, vb, out);
    kalite<<<1024, 256, sha>>>(out);
}